// round 9
// baseline (speedup 1.0000x reference)
#include <cuda_runtime.h>
#include <cuda_bf16.h>
#include <cstdint>

#define B_   64
#define S_   512
#define H_   1024
#define G_   3072
#define KP_  2048           // split layout: hi [0,1024) + lo [1024,2048)
#define MROWS (B_*S_)       // 32768, row = s*64 + b

// ---------------- persistent device scratch (no allocs allowed) -------------
__device__ __align__(256) __nv_bfloat16 g_A[(size_t)MROWS * KP_];     // layer input, split
__device__ __align__(256) __nv_bfloat16 g_Wih[2][(size_t)G_ * KP_];
__device__ __align__(256) __nv_bfloat16 g_Whh[2][(size_t)G_ * KP_];
__device__ __align__(256) float         g_Gx[(size_t)MROWS * G_];     // gate_x (+b_ih)
__device__ __align__(256) __nv_bfloat16 g_hbuf[2][2][B_][H_];         // [parity][plane][b][h]
__device__ __align__(128) unsigned g_arrive[128][8];                  // 32B-strided arrival flags
__device__ unsigned g_release;

// ---------------- PTX helpers ----------------------------------------------
__device__ __forceinline__ void cp16(void* dst, const void* src) {
    unsigned d = (unsigned)__cvta_generic_to_shared(dst);
    asm volatile("cp.async.cg.shared.global [%0], [%1], 16;\n" :: "r"(d), "l"(src));
}
__device__ __forceinline__ void cp_commit() { asm volatile("cp.async.commit_group;\n"); }
template<int N> __device__ __forceinline__ void cp_wait() {
    asm volatile("cp.async.wait_group %0;\n" :: "n"(N));
}
__device__ __forceinline__ void ldmx4(unsigned r[4], const void* p) {
    unsigned a = (unsigned)__cvta_generic_to_shared(p);
    asm volatile("ldmatrix.sync.aligned.m8n8.x4.shared.b16 {%0,%1,%2,%3}, [%4];\n"
        : "=r"(r[0]), "=r"(r[1]), "=r"(r[2]), "=r"(r[3]) : "r"(a));
}
__device__ __forceinline__ void ldmx2(unsigned r[2], const void* p) {
    unsigned a = (unsigned)__cvta_generic_to_shared(p);
    asm volatile("ldmatrix.sync.aligned.m8n8.x2.shared.b16 {%0,%1}, [%2];\n"
        : "=r"(r[0]), "=r"(r[1]) : "r"(a));
}
__device__ __forceinline__ void mma_bf16(float c[4], const unsigned a[4], const unsigned b[2]) {
    asm volatile("mma.sync.aligned.m16n8k16.row.col.f32.bf16.bf16.f32 "
        "{%0,%1,%2,%3}, {%4,%5,%6,%7}, {%8,%9}, {%0,%1,%2,%3};\n"
        : "+f"(c[0]), "+f"(c[1]), "+f"(c[2]), "+f"(c[3])
        : "r"(a[0]), "r"(a[1]), "r"(a[2]), "r"(a[3]), "r"(b[0]), "r"(b[1]));
}
__device__ __forceinline__ void split2(float v, __nv_bfloat16& hi, __nv_bfloat16& lo) {
    hi = __float2bfloat16(v);
    lo = __float2bfloat16(v - __bfloat162float(hi));
}
__device__ __forceinline__ unsigned ld_acq(const unsigned* p) {
    unsigned v;
    asm volatile("ld.global.acquire.gpu.u32 %0, [%1];" : "=r"(v) : "l"(p) : "memory");
    return v;
}
__device__ __forceinline__ void st_rel(unsigned* p, unsigned v) {
    asm volatile("st.global.release.gpu.u32 [%0], %1;" :: "l"(p), "r"(v) : "memory");
}
// Distributed-flag grid barrier: parallel release-store arrivals (32B-strided
// words), block 0 acquire-polls all flags then publishes one release word.
__device__ __forceinline__ void grid_barrier(unsigned target) {
    __syncthreads();
    if (blockIdx.x == 0) {
        int t = threadIdx.x;
        if (t >= 1 && t < 128) {
            while (ld_acq(&g_arrive[t][0]) < target) __nanosleep(32);
        }
        __syncthreads();
        if (t == 0) st_rel(&g_release, target);
    } else {
        if (threadIdx.x == 0) {
            st_rel(&g_arrive[blockIdx.x][0], target);
            while (ld_acq(&g_release) < target) __nanosleep(32);
        }
        __syncthreads();
    }
}

// ---------------- split kernels ---------------------------------------------
__global__ void split_weights_kernel(const float* __restrict__ W_ih,
                                     const float* __restrict__ W_hh) {
    const size_t per = (size_t)G_ * H_;
    const size_t total = 4 * per;
    for (size_t i = (size_t)blockIdx.x * blockDim.x + threadIdx.x; i < total;
         i += (size_t)gridDim.x * blockDim.x) {
        size_t m = i / per;
        size_t r = i - m * per;
        size_t row = r >> 10, col = r & 1023;
        const float* src = (m < 2) ? (W_ih + m * per) : (W_hh + (m - 2) * per);
        float v = src[r];
        __nv_bfloat16 hi, lo; split2(v, hi, lo);
        __nv_bfloat16* dst = (m < 2) ? g_Wih[m] : g_Whh[m - 2];
        dst[row * KP_ + col]      = hi;
        dst[row * KP_ + H_ + col] = lo;
    }
}

__global__ void split_x_kernel(const float* __restrict__ x) {
    const size_t total = (size_t)B_ * S_ * H_;
    for (size_t i = (size_t)blockIdx.x * blockDim.x + threadIdx.x; i < total;
         i += (size_t)gridDim.x * blockDim.x) {
        size_t b   = i >> 19;
        size_t rem = i & ((1u << 19) - 1);
        size_t s   = rem >> 10;
        size_t k   = rem & 1023;
        __nv_bfloat16 hi, lo; split2(x[i], hi, lo);
        size_t row = s * B_ + b;
        g_A[row * KP_ + k]      = hi;
        g_A[row * KP_ + H_ + k] = lo;
    }
}

// also resets the grid-barrier state (runs before each recurrence launch)
__global__ void split_h0_kernel(const float* __restrict__ h0, int layer) {
    if (blockIdx.x == 0 && threadIdx.x < 128) {
        g_arrive[threadIdx.x][0] = 0;
        if (threadIdx.x == 0) g_release = 0;
    }
    int i = blockIdx.x * blockDim.x + threadIdx.x;
    if (i < B_ * H_) {
        __nv_bfloat16 hi, lo; split2(h0[(size_t)layer * B_ * H_ + i], hi, lo);
        int b = i >> 10, h = i & 1023;
        g_hbuf[0][0][b][h] = hi;
        g_hbuf[0][1][b][h] = lo;
    }
}

// ---------------- bulk GEMM: g_Gx = A * W_ih^T + b_ih -----------------------
// 128x128 tile, 256 thr (8 warps 2x4), 3-stage cp.async, virtual K=3072
// (48 chunks of 64): seg0 (Ahi,Whi), seg1 (Alo,Whi), seg2 (Ahi,Wlo).
// __launch_bounds__(256, 2): cap regs at 128 so 2 CTAs co-reside per SM
// (2 x 108KB smem fits) and one CTA's mma covers the other's pipeline bubbles.
#define SMEM_GEMM (2 * 3 * 128 * 72 * 2)
__global__ __launch_bounds__(256, 2) void gemm_bulk(int layer, const float* __restrict__ bias) {
    extern __shared__ __align__(16) unsigned char smem_raw[];
    __nv_bfloat16* sA = (__nv_bfloat16*)smem_raw;      // [3][128][72]
    __nv_bfloat16* sB = sA + 3 * 128 * 72;

    const __nv_bfloat16* __restrict__ Wx = g_Wih[layer];
    int tid = threadIdx.x, lane = tid & 31, wid = tid >> 5;
    int wm = wid >> 2, wn = wid & 3;
    int m0 = blockIdx.y * 128, n0 = blockIdx.x * 128;

    float acc[4][4][4];
#pragma unroll
    for (int a = 0; a < 4; ++a)
#pragma unroll
        for (int b = 0; b < 4; ++b)
#pragma unroll
            for (int c = 0; c < 4; ++c) acc[a][b][c] = 0.f;

    int lr = tid >> 3, lq = tid & 7;   // 32 rows x 8 col-groups

    auto issue = [&](int c, int st) {
        int seg = c >> 4, kc = c & 15;
        int aCol = ((seg == 1) ? H_ : 0) + kc * 64 + lq * 8;
        int bCol = ((seg == 2) ? H_ : 0) + kc * 64 + lq * 8;
#pragma unroll
        for (int q = 0; q < 4; ++q) {
            int r = lr + q * 32;
            cp16(&sA[(st * 128 + r) * 72 + lq * 8], g_A + (size_t)(m0 + r) * KP_ + aCol);
            cp16(&sB[(st * 128 + r) * 72 + lq * 8], Wx  + (size_t)(n0 + r) * KP_ + bCol);
        }
        cp_commit();
    };

    issue(0, 0); issue(1, 1);
    for (int c = 0; c < 48; ++c) {
        if (c < 47) cp_wait<1>(); else cp_wait<0>();
        __syncthreads();
        if (c + 2 < 48) issue(c + 2, (c + 2) % 3);
        int st = c % 3;
#pragma unroll
        for (int kk = 0; kk < 4; ++kk) {
            unsigned af[4][4], bfr[4][2];
#pragma unroll
            for (int mt = 0; mt < 4; ++mt)
                ldmx4(af[mt], &sA[(st * 128 + wm * 64 + mt * 16 + (lane & 15)) * 72 + kk * 16 + ((lane >> 4) << 3)]);
#pragma unroll
            for (int nt = 0; nt < 4; ++nt)
                ldmx2(bfr[nt], &sB[(st * 128 + wn * 32 + nt * 8 + (lane & 7)) * 72 + kk * 16 + (((lane >> 3) & 1) << 3)]);
#pragma unroll
            for (int mt = 0; mt < 4; ++mt)
#pragma unroll
                for (int nt = 0; nt < 4; ++nt)
                    mma_bf16(acc[mt][nt], af[mt], bfr[nt]);
        }
    }
#pragma unroll
    for (int mt = 0; mt < 4; ++mt) {
        int mrow = m0 + wm * 64 + mt * 16 + (lane >> 2);
#pragma unroll
        for (int nt = 0; nt < 4; ++nt) {
            int ncol = n0 + wn * 32 + nt * 8 + (lane & 3) * 2;
            float b0 = __ldg(bias + ncol), b1 = __ldg(bias + ncol + 1);
            float* o  = g_Gx + (size_t)mrow * G_ + ncol;
            float* o8 = o + (size_t)8 * G_;
            o[0]  = acc[mt][nt][0] + b0;
            o[1]  = acc[mt][nt][1] + b1;
            o8[0] = acc[mt][nt][2] + b0;
            o8[1] = acc[mt][nt][3] + b1;
        }
    }
}

// ---------------- persistent recurrence -------------------------------------
// 128 blocks x 384 thr (12 warps: 4 m-strips x 3 gate-tiles). Block owns 8
// hidden units -> 24 W_hh rows resident in SMEM for all 512 steps.
// h streamed in 16 chunks/step (8 hi + 8 lo); hi chunks feed TWO mma passes
// (W-hi and W-lo columns) sharing one A fragment; lo chunks one (W-hi).
// Commit order per step: h0, h1, THEN the gate_x/h_prev prefetch (DRAM-latency
// prefetch must not gate the first h-chunk drain; groups retire FIFO).
// Combine: 256 threads x 2 adjacent units -> all stores 4B/8B vectorized.
#define SW_STRIDE 2056
#define SH_STRIDE 136
#define SMEM_REC  (24*SW_STRIDE*2 + 3*64*SH_STRIDE*2 + 64*25*4 + 24*4 + 64*24*4 + 64*16*2)
__global__ __launch_bounds__(384) void gru_recurrence(int layer,
        const float* __restrict__ bhh, float* __restrict__ out) {
    extern __shared__ __align__(16) unsigned char smem_raw[];
    __nv_bfloat16* sW   = (__nv_bfloat16*)smem_raw;            // [24][2056]
    __nv_bfloat16* sH   = sW + 24 * SW_STRIDE;                 // [3][64][136]
    float*         sG   = (float*)(sH + 3 * 64 * SH_STRIDE);   // [64][25] gate_h (STS)
    float*         sBias= sG + 64 * 25;                        // [24]
    float*         sGX  = sBias + 24;                          // [64][24] gate_x (cp.async, stride 96B)
    __nv_bfloat16* sPRE = (__nv_bfloat16*)(sGX + 64 * 24);     // [64][16] h_prev hi/lo

    const int tid = threadIdx.x, lane = tid & 31, wid = tid >> 5;
    const int wm = wid & 3, wn = wid >> 2;                     // 4 x 3
    const int j0 = blockIdx.x * 8;
    const __nv_bfloat16* __restrict__ Wg = g_Whh[layer];

    // load W_hh slice: rows (gate g, unit j0+u) for g in {0,1,2}, u in [0,8)
    for (int i = tid; i < 24 * 2048; i += 384) {
        int r = i >> 11, c = i & 2047;
        int grow = (r >> 3) * H_ + j0 + (r & 7);
        sW[r * SW_STRIDE + c] = Wg[(size_t)grow * KP_ + c];
    }
    if (tid < 24) sBias[tid] = bhh[(tid >> 3) * H_ + j0 + (tid & 7)];
    __syncthreads();

    // prefetch thread mapping (one cp16 each): tid -> (b, gate, half4)
    const int pf_b = tid / 6, pf_rem = tid - pf_b * 6;
    const int pf_gate = pf_rem >> 1, pf_half = pf_rem & 1;

    for (int s = 0; s < S_; ++s) {
        const int par = s & 1;
        float acc[4] = {0.f, 0.f, 0.f, 0.f};

        // chunk c in [0,16): plane = c>>3 (0=hi, 1=lo), kc = c&7
        auto issueH = [&](int c, int st) {
            if (tid < 256) {
                int plane = c >> 3, kc = c & 7;
                int row = tid >> 2, coll = (tid & 3) * 8;
                const __nv_bfloat16* src = &g_hbuf[par][plane][row][kc * 128 + coll];
                __nv_bfloat16* dst = &sH[(st * 64 + row) * SH_STRIDE + coll];
                cp16(dst, src); cp16(dst + 32, src + 32);
                cp16(dst + 64, src + 64); cp16(dst + 96, src + 96);
            }
            cp_commit();
        };

        issueH(0, 0); issueH(1, 1);

        // ---- prefetch group: gate_x (64x24 f32) + h_prev (64x16 bf16) ----
        // Committed AFTER h0/h1 so the g_Gx DRAM read never gates h0's drain.
        {
            const float* gsrc = g_Gx + (size_t)(s * 64 + pf_b) * G_ + pf_gate * H_ + j0 + pf_half * 4;
            cp16(&sGX[pf_b * 24 + pf_gate * 8 + pf_half * 4], gsrc);
            if (tid < 128) {
                int b = tid >> 1, plane = tid & 1;
                cp16(&sPRE[b * 16 + plane * 8], &g_hbuf[par][plane][b][j0]);
            }
            cp_commit();
        }

        for (int c = 0; c < 16; ++c) {
            if (c < 15) cp_wait<1>(); else cp_wait<0>();
            __syncthreads();
            if (c + 2 < 16) issueH(c + 2, (c + 2) % 3);
            int st = c % 3;
            int plane = c >> 3, kc = c & 7;
            int wcb_hi = kc * 128;           // W-hi columns
            int wcb_lo = H_ + kc * 128;      // W-lo columns
#pragma unroll
            for (int kk = 0; kk < 8; ++kk) {
                unsigned af[4], bhi[2];
                ldmx4(af,  &sH[(st * 64 + wm * 16 + (lane & 15)) * SH_STRIDE + kk * 16 + ((lane >> 4) << 3)]);
                ldmx2(bhi, &sW[(wn * 8 + (lane & 7)) * SW_STRIDE + wcb_hi + kk * 16 + (((lane >> 3) & 1) << 3)]);
                mma_bf16(acc, af, bhi);      // hi*Whi  or  lo*Whi
                if (plane == 0) {
                    unsigned blo[2];
                    ldmx2(blo, &sW[(wn * 8 + (lane & 7)) * SW_STRIDE + wcb_lo + kk * 16 + (((lane >> 3) & 1) << 3)]);
                    mma_bf16(acc, af, blo);  // hi*Wlo
                }
            }
        }
        {   // stash gate_h fragment
            int m = wm * 16 + (lane >> 2);
            int n = wn * 8 + (lane & 3) * 2;
            sG[m * 25 + n]           = acc[0];
            sG[m * 25 + n + 1]       = acc[1];
            sG[(m + 8) * 25 + n]     = acc[2];
            sG[(m + 8) * 25 + n + 1] = acc[3];
        }
        __syncthreads();

        // combine: 256 threads x 2 adjacent units (jj even) — smem reads,
        // vectorized 4B/8B global stores
        if (tid < 256) {
            int b = tid >> 2, j = (tid & 3) * 2, jj = j0 + j;
            float hnew2[2];
#pragma unroll
            for (int u = 0; u < 2; ++u) {
                int ju = j + u;
                float hr = sG[b * 25 + ju]      + sBias[ju];
                float hz = sG[b * 25 + 8 + ju]  + sBias[8 + ju];
                float hn = sG[b * 25 + 16 + ju] + sBias[16 + ju];
                float hprev = __bfloat162float(sPRE[b * 16 + ju])
                            + __bfloat162float(sPRE[b * 16 + 8 + ju]);
                float r = 1.f / (1.f + __expf(-(sGX[b * 24 + ju] + hr)));
                float z = 1.f / (1.f + __expf(-(sGX[b * 24 + 8 + ju] + hz)));
                float n = tanhf(sGX[b * 24 + 16 + ju] + r * hn);
                hnew2[u] = n + z * (hprev - n);
            }
            __nv_bfloat16 hi0, lo0, hi1, lo1;
            split2(hnew2[0], hi0, lo0);
            split2(hnew2[1], hi1, lo1);
            __nv_bfloat162 hpack = {hi0, hi1}, lpack = {lo0, lo1};
            *reinterpret_cast<__nv_bfloat162*>(&g_hbuf[par ^ 1][0][b][jj]) = hpack;
            *reinterpret_cast<__nv_bfloat162*>(&g_hbuf[par ^ 1][1][b][jj]) = lpack;
            if (layer == 0) {
                size_t row = (size_t)s * 64 + b;
                *reinterpret_cast<__nv_bfloat162*>(&g_A[row * KP_ + jj])      = hpack;
                *reinterpret_cast<__nv_bfloat162*>(&g_A[row * KP_ + H_ + jj]) = lpack;
            } else {
                float2 o2 = {hnew2[0], hnew2[1]};
                *reinterpret_cast<float2*>(&out[((size_t)b * S_ + s) * H_ + jj]) = o2;
            }
            if (s == S_ - 1) {
                float2 o2 = {hnew2[0], hnew2[1]};
                *reinterpret_cast<float2*>(
                    &out[(size_t)B_ * S_ * H_ + (size_t)layer * B_ * H_ + (size_t)b * H_ + jj]) = o2;
            }
        }
        if (s + 1 < S_) grid_barrier((unsigned)(s + 1));
    }
}

// ---------------- host ------------------------------------------------------
extern "C" void kernel_launch(void* const* d_in, const int* in_sizes, int n_in,
                              void* d_out, int out_size) {
    const float* x    = (const float*)d_in[0];
    const float* h0   = (const float*)d_in[1];
    const float* W_ih = (const float*)d_in[2];
    const float* W_hh = (const float*)d_in[3];
    const float* b_ih = (const float*)d_in[4];
    const float* b_hh = (const float*)d_in[5];
    float* out = (float*)d_out;
    (void)in_sizes; (void)n_in; (void)out_size;

    cudaFuncSetAttribute(gemm_bulk, cudaFuncAttributeMaxDynamicSharedMemorySize, SMEM_GEMM);
    cudaFuncSetAttribute(gru_recurrence, cudaFuncAttributeMaxDynamicSharedMemorySize, SMEM_REC);

    split_weights_kernel<<<2048, 256>>>(W_ih, W_hh);
    split_x_kernel<<<4096, 256>>>(x);

    for (int layer = 0; layer < 2; ++layer) {
        gemm_bulk<<<dim3(24, 256), 256, SMEM_GEMM>>>(layer, b_ih + layer * G_);
        split_h0_kernel<<<64, 1024>>>(h0, layer);   // also resets grid-barrier state
        gru_recurrence<<<128, 384, SMEM_REC>>>(layer, b_hh + layer * G_, out);
    }
}